// round 16
// baseline (speedup 1.0000x reference)
#include <cuda_runtime.h>
#include <cuda_bf16.h>
#include <math.h>

// ---------------- problem constants ----------------
#define NN    50000
#define EE    800000
#define FF    128
#define HH    4
#define CC    32
#define HCW   128
#define LINW  256
#define OUTW  10
#define GG    64
#define NEG   0.2f
#define SB    ((NN + 1023) / 1024)   // 49 scan blocks

// ---------------- device scratch ----------------
__device__ float    g_h[NN * HCW];
__device__ float    g_out[NN * HCW];
__device__ float    g_asrc[NN * HH];
__device__ float    g_adst[NN * HH];
__device__ float    g_pool[GG * HCW];
__device__ int      g_is64;
__device__ unsigned g_gmax_enc[3];
__device__ int      g_deg[NN];          // zero at call entry (leave-clean invariant)
__device__ int      g_row[NN + 1];
__device__ int      g_csr[EE];
__device__ int      g_bsum[SB];

// ---------------- helpers ----------------
__device__ __forceinline__ float lrelu(float x) { return x > 0.f ? x : NEG * x; }

__device__ __forceinline__ unsigned fenc(float f) {
    unsigned u = __float_as_uint(f);
    return (u & 0x80000000u) ? ~u : (u | 0x80000000u);
}
__device__ __forceinline__ float fdec(unsigned u) {
    return __uint_as_float((u & 0x80000000u) ? (u & 0x7fffffffu) : ~u);
}
#define ENC_NEGINF 0x007fffffu

__device__ __forceinline__ int edge_idx(const void* __restrict__ ei, long long pos, int is64) {
    return is64 ? (int)((const long long*)ei)[pos] : ((const int*)ei)[pos];
}

// packed fp32x2 helpers
__device__ __forceinline__ unsigned long long pk2(float a, float b) {
    unsigned long long r;
    asm("mov.b64 %0, {%1,%2};" : "=l"(r) : "f"(a), "f"(b));
    return r;
}
__device__ __forceinline__ void upk2(unsigned long long v, float& a, float& b) {
    asm("mov.b64 {%0,%1}, %2;" : "=f"(a), "=f"(b) : "l"(v));
}
__device__ __forceinline__ void fma2(unsigned long long& d,
                                     unsigned long long a, unsigned long long b) {
    asm("fma.rn.f32x2 %0, %1, %2, %0;" : "+l"(d) : "l"(a), "l"(b));
}

// ---------------- init: pool zero, gmax reset, dtype detect ----------------
__global__ void k_init(const unsigned* __restrict__ ei_words) {
    int i = blockIdx.x * blockDim.x + threadIdx.x;
    if (i < GG * HCW) g_pool[i] = 0.f;
    if (i < 3) g_gmax_enc[i] = ENC_NEGINF;
    if (i == 0) {
        unsigned acc = 0;
        for (int j = 1; j < 256; j += 2) acc |= ei_words[j];
        g_is64 = (acc == 0u) ? 1 : 0;
    }
}

// ---------------- CSR build ----------------
__global__ __launch_bounds__(256) void k_hist(const void* __restrict__ ei) {
    int e = blockIdx.x * blockDim.x + threadIdx.x;
    if (e >= EE) return;
    int d = edge_idx(ei, (long long)EE + e, g_is64);
    atomicAdd(&g_deg[d], 1);
}

__global__ __launch_bounds__(1024) void k_scan1() {
    __shared__ int s[1024];
    int t = threadIdx.x, i = blockIdx.x * 1024 + t;
    s[t] = (i < NN) ? g_deg[i] : 0;
    __syncthreads();
    for (int off = 512; off; off >>= 1) {
        if (t < off) s[t] += s[t + off];
        __syncthreads();
    }
    if (t == 0) g_bsum[blockIdx.x] = s[0];
}

__global__ __launch_bounds__(1024) void k_scan3() {
    __shared__ int s[1024];
    __shared__ int boff;
    int t = threadIdx.x, i = blockIdx.x * 1024 + t;
    if (t == 0) {
        int run = 0;
        for (int b = 0; b < blockIdx.x; b++) run += g_bsum[b];
        boff = run;
    }
    int v = (i < NN) ? g_deg[i] : 0;
    s[t] = v;
    __syncthreads();
    for (int off = 1; off < 1024; off <<= 1) {
        int u = (t >= off) ? s[t - off] : 0;
        __syncthreads();
        s[t] += u;
        __syncthreads();
    }
    if (i < NN) {
        g_row[i + 1] = boff + s[t];
        g_deg[i] = 0;                 // reuse as scatter cursor
    }
    if (i == 0) g_row[0] = 0;
}

__global__ __launch_bounds__(256) void k_scatter(const void* __restrict__ ei) {
    int e = blockIdx.x * blockDim.x + threadIdx.x;
    if (e >= EE) return;
    int is64 = g_is64;
    int s = edge_idx(ei, e, is64);
    int d = edge_idx(ei, (long long)EE + e, is64);
    int pos = g_row[d] + atomicAdd(&g_deg[d], 1);
    g_csr[pos] = s;
}

// ---------------- GEMM + fused alpha ----------------
// Round-13 structure; x now staged DUPLICATED in smem (float2(v,v)) so the
// packed fp32x2 operand comes from one broadcast LDS.64 (no per-k MOV pair).
// Dynamic smem: Ws 16KB + Xsd 33KB = ~49KB, 2 blocks/SM.
#define GEMM_SMEM (16384 + 128 * 33 * 8)
__global__ __launch_bounds__(256, 2) void k_gemm(const float* __restrict__ inp,
                                                 const float* __restrict__ W,
                                                 const float* __restrict__ bias,
                                                 int use_gout,
                                                 const float* __restrict__ as,
                                                 const float* __restrict__ ad,
                                                 int layer) {
    extern __shared__ char dsm[];
    float*  Ws  = (float*)dsm;                      // [k][n] panel, 32x128
    float2* Xsd = (float2*)(dsm + 16384);           // [row][k] dup pairs, stride 33

    const float* in = use_gout ? g_out : inp;
    const int tid = threadIdx.x;
    const int cg  = tid & 15;
    const int rg  = tid >> 4;
    const int r0  = blockIdx.x * 128;

    float4* Ws4 = (float4*)Ws;
    const float4* W4  = (const float4*)W;
    const float4* in4 = (const float4*)in;
    const float4* b4  = (const float4*)bias;

    unsigned long long acc2[8][4];
#pragma unroll
    for (int r = 0; r < 8; r++)
#pragma unroll
        for (int c = 0; c < 4; c++) acc2[r][c] = 0ull;

    for (int kk = 0; kk < 128; kk += 32) {
#pragma unroll
        for (int i = tid; i < 1024; i += 256)
            Ws4[i] = W4[(kk + (i >> 5)) * 32 + (i & 31)];
#pragma unroll
        for (int i = tid; i < 1024; i += 256) {
            int row = i >> 3, j = i & 7;
            int gr = r0 + row;
            float4 v = make_float4(0.f, 0.f, 0.f, 0.f);
            if (gr < NN) {
                v = in4[gr * 32 + (kk >> 2) + j];
                if (bias) {
                    float4 bb = b4[(kk >> 2) + j];
                    v.x = fmaxf(v.x + bb.x, 0.f);
                    v.y = fmaxf(v.y + bb.y, 0.f);
                    v.z = fmaxf(v.z + bb.z, 0.f);
                    v.w = fmaxf(v.w + bb.w, 0.f);
                }
            }
            float2* xp = &Xsd[row * 33 + j * 4];
            xp[0] = make_float2(v.x, v.x);
            xp[1] = make_float2(v.y, v.y);
            xp[2] = make_float2(v.z, v.z);
            xp[3] = make_float2(v.w, v.w);
        }
        __syncthreads();

#pragma unroll
        for (int k = 0; k < 32; k++) {
            float4 wa = Ws4[k * 32 + cg * 2];
            float4 wb = Ws4[k * 32 + cg * 2 + 1];
            unsigned long long w0 = pk2(wa.x, wa.y);
            unsigned long long w1 = pk2(wa.z, wa.w);
            unsigned long long w2 = pk2(wb.x, wb.y);
            unsigned long long w3 = pk2(wb.z, wb.w);
#pragma unroll
            for (int r = 0; r < 8; r++) {
                unsigned long long xp =
                    *(const unsigned long long*)&Xsd[(rg * 8 + r) * 33 + k];
                fma2(acc2[r][0], xp, w0);
                fma2(acc2[r][1], xp, w1);
                fma2(acc2[r][2], xp, w2);
                fma2(acc2[r][3], xp, w3);
            }
        }
        __syncthreads();
    }

    // ---- epilogue: store h, alphas, block max ----
    const float4* as4 = (const float4*)as;
    const float4* ad4 = (const float4*)ad;
    float4 A0 = as4[cg * 2], A1 = as4[cg * 2 + 1];
    float4 D0 = ad4[cg * 2], D1 = ad4[cg * 2 + 1];
    float4* out4 = (float4*)g_h;
    float mxl = -INFINITY;
    const int head = cg >> 2;
    const bool lead = (cg & 3) == 0;

#pragma unroll
    for (int r = 0; r < 8; r++) {
        float a0, a1, a2, a3, a4, a5, a6, a7;
        upk2(acc2[r][0], a0, a1);
        upk2(acc2[r][1], a2, a3);
        upk2(acc2[r][2], a4, a5);
        upk2(acc2[r][3], a6, a7);
        float ps = a0 * A0.x + a1 * A0.y + a2 * A0.z + a3 * A0.w
                 + a4 * A1.x + a5 * A1.y + a6 * A1.z + a7 * A1.w;
        float pd = a0 * D0.x + a1 * D0.y + a2 * D0.z + a3 * D0.w
                 + a4 * D1.x + a5 * D1.y + a6 * D1.z + a7 * D1.w;
        ps += __shfl_xor_sync(0xffffffffu, ps, 1);
        ps += __shfl_xor_sync(0xffffffffu, ps, 2);
        pd += __shfl_xor_sync(0xffffffffu, pd, 1);
        pd += __shfl_xor_sync(0xffffffffu, pd, 2);
        int gr = r0 + rg * 8 + r;
        if (gr < NN) {
            out4[gr * 32 + cg * 2]     = make_float4(a0, a1, a2, a3);
            out4[gr * 32 + cg * 2 + 1] = make_float4(a4, a5, a6, a7);
            if (lead) {
                g_asrc[gr * 4 + head] = ps;
                g_adst[gr * 4 + head] = pd;
                mxl = fmaxf(mxl, ps);
            }
        }
    }

    __syncthreads();
    float* sred = Ws;     // reuse smem
    sred[tid] = mxl;
    __syncthreads();
    for (int s = 128; s; s >>= 1) {
        if (tid < s) sred[tid] = fmaxf(sred[tid], sred[tid + s]);
        __syncthreads();
    }
    if (tid == 0) atomicMax(&g_gmax_enc[layer], fenc(sred[0]));
}

// ---------------- fused softmax + aggregation: 4 dst nodes per warp ----------------
// (round-13 proven, unchanged)
__global__ __launch_bounds__(256) void k_aggr(int layer,
                                              const void* __restrict__ batch,
                                              const float* __restrict__ b2) {
    int w    = (blockIdx.x * blockDim.x + threadIdx.x) >> 5;
    int lane = threadIdx.x & 31;
    int grp  = lane >> 3;
    int gl   = lane & 7;
    int d    = w * 4 + grp;
    if (d >= NN) return;

    float gmax = fdec(g_gmax_enc[layer]);
    float4 adv = ((const float4*)g_adst)[d];
    float m0 = lrelu(gmax + adv.x);
    float m1 = lrelu(gmax + adv.y);
    float m2 = lrelu(gmax + adv.z);
    float m3 = lrelu(gmax + adv.w);

    int beg = g_row[d];
    int cnt = g_row[d + 1] - beg;
    if (layer == 0 && gl == 0) g_deg[d] = 0;    // leave-clean for next call

    int tmax = cnt;
    tmax = max(tmax, __shfl_xor_sync(0xffffffffu, tmax, 8));
    tmax = max(tmax, __shfl_xor_sync(0xffffffffu, tmax, 16));

    float4 acc0 = make_float4(0.f, 0.f, 0.f, 0.f);
    float4 acc1 = acc0, acc2 = acc0, acc3 = acc0;
    float den0 = 0.f, den1 = 0.f, den2 = 0.f, den3 = 0.f;
    const float4* h4  = (const float4*)g_h;
    const float4* as4 = (const float4*)g_asrc;

    for (int t = 0; t < tmax; t += 2) {
#pragma unroll
        for (int u = 0; u < 2; u++) {
            int tt = t + u;
            if (tt < cnt) {
                int s = g_csr[beg + tt];
                float4 av = as4[s];
                float e0 = __expf(lrelu(av.x + adv.x) - m0);
                float e1 = __expf(lrelu(av.y + adv.y) - m1);
                float e2 = __expf(lrelu(av.z + adv.z) - m2);
                float e3 = __expf(lrelu(av.w + adv.w) - m3);
                float4 h0 = h4[s * 32 + gl];
                float4 h1 = h4[s * 32 + gl + 8];
                float4 h2 = h4[s * 32 + gl + 16];
                float4 h3 = h4[s * 32 + gl + 24];
                den0 += e0; den1 += e1; den2 += e2; den3 += e3;
                acc0.x += e0 * h0.x; acc0.y += e0 * h0.y; acc0.z += e0 * h0.z; acc0.w += e0 * h0.w;
                acc1.x += e1 * h1.x; acc1.y += e1 * h1.y; acc1.z += e1 * h1.z; acc1.w += e1 * h1.w;
                acc2.x += e2 * h2.x; acc2.y += e2 * h2.y; acc2.z += e2 * h2.z; acc2.w += e2 * h2.w;
                acc3.x += e3 * h3.x; acc3.y += e3 * h3.y; acc3.z += e3 * h3.z; acc3.w += e3 * h3.w;
            }
        }
    }
    // self loop (s = d)
    {
        float4 av = as4[d];
        float e0 = __expf(lrelu(av.x + adv.x) - m0);
        float e1 = __expf(lrelu(av.y + adv.y) - m1);
        float e2 = __expf(lrelu(av.z + adv.z) - m2);
        float e3 = __expf(lrelu(av.w + adv.w) - m3);
        float4 h0 = h4[d * 32 + gl];
        float4 h1 = h4[d * 32 + gl + 8];
        float4 h2 = h4[d * 32 + gl + 16];
        float4 h3 = h4[d * 32 + gl + 24];
        den0 += e0; den1 += e1; den2 += e2; den3 += e3;
        acc0.x += e0 * h0.x; acc0.y += e0 * h0.y; acc0.z += e0 * h0.z; acc0.w += e0 * h0.w;
        acc1.x += e1 * h1.x; acc1.y += e1 * h1.y; acc1.z += e1 * h1.z; acc1.w += e1 * h1.w;
        acc2.x += e2 * h2.x; acc2.y += e2 * h2.y; acc2.z += e2 * h2.z; acc2.w += e2 * h2.w;
        acc3.x += e3 * h3.x; acc3.y += e3 * h3.y; acc3.z += e3 * h3.z; acc3.w += e3 * h3.w;
    }

    float i0 = 1.f / den0, i1 = 1.f / den1, i2 = 1.f / den2, i3 = 1.f / den3;
    float4 o0 = make_float4(acc0.x * i0, acc0.y * i0, acc0.z * i0, acc0.w * i0);
    float4 o1 = make_float4(acc1.x * i1, acc1.y * i1, acc1.z * i1, acc1.w * i1);
    float4 o2 = make_float4(acc2.x * i2, acc2.y * i2, acc2.z * i2, acc2.w * i2);
    float4 o3 = make_float4(acc3.x * i3, acc3.y * i3, acc3.z * i3, acc3.w * i3);

    if (layer < 2) {
        float4* out4 = (float4*)g_out;
        out4[d * 32 + gl]      = o0;
        out4[d * 32 + gl + 8]  = o1;
        out4[d * 32 + gl + 16] = o2;
        out4[d * 32 + gl + 24] = o3;
    } else {
        int g = g_is64 ? (int)((const long long*)batch)[d] : ((const int*)batch)[d];
        const float4* b24 = (const float4*)b2;
        float4 bb0 = b24[gl], bb1 = b24[gl + 8], bb2 = b24[gl + 16], bb3 = b24[gl + 24];
        int* pp = (int*)&g_pool[g * 128];
#pragma unroll 4
        for (int i = 0; i < 4; i++) {
            float4 o  = (i == 0) ? o0 : (i == 1) ? o1 : (i == 2) ? o2 : o3;
            float4 bb = (i == 0) ? bb0 : (i == 1) ? bb1 : (i == 2) ? bb2 : bb3;
            int c = (gl + 8 * i) * 4;
            atomicMax(&pp[c + 0], __float_as_int(fmaxf(o.x + bb.x, 0.f)));
            atomicMax(&pp[c + 1], __float_as_int(fmaxf(o.y + bb.y, 0.f)));
            atomicMax(&pp[c + 2], __float_as_int(fmaxf(o.z + bb.z, 0.f)));
            atomicMax(&pp[c + 3], __float_as_int(fmaxf(o.w + bb.w, 0.f)));
        }
    }
}

// ---------------- fused MLP tail: per-graph block ----------------
__global__ __launch_bounds__(256) void k_lin(const float* __restrict__ Wlin,
                                             const float* __restrict__ blin,
                                             const float* __restrict__ Wout,
                                             const float* __restrict__ bout,
                                             float* __restrict__ out) {
    __shared__ float sp[128];
    __shared__ float z[256];
    int g = blockIdx.x, t = threadIdx.x;
    if (t < 128) sp[t] = g_pool[g * 128 + t];
    __syncthreads();
    float acc = blin[t];
    for (int k = 0; k < 128; k++) acc += sp[k] * Wlin[k * 256 + t];
    z[t] = acc;
    __syncthreads();
    if (t < OUTW) {
        float o = bout[t];
        for (int k = 0; k < 256; k++) o += z[k] * Wout[k * OUTW + t];
        out[g * OUTW + t] = o;
    }
}

// ---------------- host launcher ----------------
extern "C" void kernel_launch(void* const* d_in, const int* in_sizes, int n_in,
                              void* d_out, int out_size) {
    const float* x    = (const float*)d_in[0];
    const void*  ei   = d_in[1];
    const void*  batch= d_in[2];
    const float* W0   = (const float*)d_in[3];
    const float* as0  = (const float*)d_in[4];
    const float* ad0  = (const float*)d_in[5];
    const float* b0   = (const float*)d_in[6];
    const float* W1   = (const float*)d_in[7];
    const float* as1  = (const float*)d_in[8];
    const float* ad1  = (const float*)d_in[9];
    const float* b1   = (const float*)d_in[10];
    const float* W2   = (const float*)d_in[11];
    const float* as2  = (const float*)d_in[12];
    const float* ad2  = (const float*)d_in[13];
    const float* b2   = (const float*)d_in[14];
    const float* Wlin = (const float*)d_in[15];
    const float* blin = (const float*)d_in[16];
    const float* Wout = (const float*)d_in[17];
    const float* bout = (const float*)d_in[18];

    const float* Ws[3]  = {W0, W1, W2};
    const float* ass[3] = {as0, as1, as2};
    const float* ads[3] = {ad0, ad1, ad2};
    const float* bp[3]  = {nullptr, b0, b1};

    cudaFuncSetAttribute(k_gemm, cudaFuncAttributeMaxDynamicSharedMemorySize,
                         GEMM_SMEM);

    k_init<<<32, 256>>>((const unsigned*)ei);
    k_hist<<<(EE + 255) / 256, 256>>>(ei);
    k_scan1<<<SB, 1024>>>();
    k_scan3<<<SB, 1024>>>();
    k_scatter<<<(EE + 255) / 256, 256>>>(ei);

    const int gemm_blocks = (NN + 127) / 128;
    const int aggr_blocks = ((NN + 3) / 4 * 32 + 255) / 256;

    for (int l = 0; l < 3; l++) {
        k_gemm<<<gemm_blocks, 256, GEMM_SMEM>>>(x, Ws[l], bp[l], (l != 0) ? 1 : 0,
                                                ass[l], ads[l], l);
        k_aggr<<<aggr_blocks, 256>>>(l, batch, b2);
    }

    k_lin<<<GG, 256>>>(Wlin, blin, Wout, bout, (float*)d_out);
}

// round 17
// speedup vs baseline: 1.1945x; 1.1945x over previous
#include <cuda_runtime.h>
#include <cuda_bf16.h>
#include <math.h>

// ---------------- problem constants ----------------
#define NN    50000
#define EE    800000
#define FF    128
#define HH    4
#define CC    32
#define HCW   128
#define LINW  256
#define OUTW  10
#define GG    64
#define NEG   0.2f
#define SB    ((NN + 1023) / 1024)   // 49 scan blocks

// ---------------- device scratch ----------------
__device__ float    g_h[NN * HCW];
__device__ float    g_out[NN * HCW];
__device__ float    g_asrc[NN * HH];
__device__ float    g_adst[NN * HH];
__device__ float    g_pool[GG * HCW];
__device__ int      g_is64;
__device__ unsigned g_gmax_enc[3];
__device__ int      g_deg[NN];          // zero at call entry (leave-clean invariant)
__device__ int      g_row[NN + 1];
__device__ int      g_csr[EE];
__device__ int      g_bsum[SB];

// ---------------- helpers ----------------
__device__ __forceinline__ float lrelu(float x) { return x > 0.f ? x : NEG * x; }

__device__ __forceinline__ unsigned fenc(float f) {
    unsigned u = __float_as_uint(f);
    return (u & 0x80000000u) ? ~u : (u | 0x80000000u);
}
__device__ __forceinline__ float fdec(unsigned u) {
    return __uint_as_float((u & 0x80000000u) ? (u & 0x7fffffffu) : ~u);
}
#define ENC_NEGINF 0x007fffffu

__device__ __forceinline__ int edge_idx(const void* __restrict__ ei, long long pos, int is64) {
    return is64 ? (int)((const long long*)ei)[pos] : ((const int*)ei)[pos];
}

// packed fp32x2 helpers
__device__ __forceinline__ unsigned long long pk2(float a, float b) {
    unsigned long long r;
    asm("mov.b64 %0, {%1,%2};" : "=l"(r) : "f"(a), "f"(b));
    return r;
}
__device__ __forceinline__ void upk2(unsigned long long v, float& a, float& b) {
    asm("mov.b64 {%0,%1}, %2;" : "=f"(a), "=f"(b) : "l"(v));
}
__device__ __forceinline__ void fma2(unsigned long long& d,
                                     unsigned long long a, unsigned long long b) {
    asm("fma.rn.f32x2 %0, %1, %2, %0;" : "+l"(d) : "l"(a), "l"(b));
}

// ---------------- init: pool zero, gmax reset, dtype detect ----------------
__global__ void k_init(const unsigned* __restrict__ ei_words) {
    int i = blockIdx.x * blockDim.x + threadIdx.x;
    if (i < GG * HCW) g_pool[i] = 0.f;
    if (i < 3) g_gmax_enc[i] = ENC_NEGINF;
    if (i == 0) {
        unsigned acc = 0;
        for (int j = 1; j < 256; j += 2) acc |= ei_words[j];
        g_is64 = (acc == 0u) ? 1 : 0;
    }
}

// ---------------- CSR build ----------------
__global__ __launch_bounds__(256) void k_hist(const void* __restrict__ ei) {
    int e = blockIdx.x * blockDim.x + threadIdx.x;
    if (e >= EE) return;
    int d = edge_idx(ei, (long long)EE + e, g_is64);
    atomicAdd(&g_deg[d], 1);
}

__global__ __launch_bounds__(1024) void k_scan1() {
    __shared__ int s[1024];
    int t = threadIdx.x, i = blockIdx.x * 1024 + t;
    s[t] = (i < NN) ? g_deg[i] : 0;
    __syncthreads();
    for (int off = 512; off; off >>= 1) {
        if (t < off) s[t] += s[t + off];
        __syncthreads();
    }
    if (t == 0) g_bsum[blockIdx.x] = s[0];
}

__global__ __launch_bounds__(1024) void k_scan3() {
    __shared__ int s[1024];
    __shared__ int boff;
    int t = threadIdx.x, i = blockIdx.x * 1024 + t;
    if (t == 0) {
        int run = 0;
        for (int b = 0; b < blockIdx.x; b++) run += g_bsum[b];
        boff = run;
    }
    int v = (i < NN) ? g_deg[i] : 0;
    s[t] = v;
    __syncthreads();
    for (int off = 1; off < 1024; off <<= 1) {
        int u = (t >= off) ? s[t - off] : 0;
        __syncthreads();
        s[t] += u;
        __syncthreads();
    }
    if (i < NN) {
        g_row[i + 1] = boff + s[t];
        g_deg[i] = 0;                 // reuse as scatter cursor
    }
    if (i == 0) g_row[0] = 0;
}

__global__ __launch_bounds__(256) void k_scatter(const void* __restrict__ ei) {
    int e = blockIdx.x * blockDim.x + threadIdx.x;
    if (e >= EE) return;
    int is64 = g_is64;
    int s = edge_idx(ei, e, is64);
    int d = edge_idx(ei, (long long)EE + e, is64);
    int pos = g_row[d] + atomicAdd(&g_deg[d], 1);
    g_csr[pos] = s;
}

// ---------------- GEMM + fused alpha (round-13 proven, FROZEN) ----------------
__global__ __launch_bounds__(256, 2) void k_gemm(const float* __restrict__ inp,
                                                 const float* __restrict__ W,
                                                 const float* __restrict__ bias,
                                                 int use_gout,
                                                 const float* __restrict__ as,
                                                 const float* __restrict__ ad,
                                                 int layer) {
    __shared__ float Ws[32 * 128];       // panel [k][n]
    __shared__ float Xs[128 * 33];       // [row][k], stride 33

    const float* in = use_gout ? g_out : inp;
    const int tid = threadIdx.x;
    const int cg  = tid & 15;
    const int rg  = tid >> 4;
    const int r0  = blockIdx.x * 128;

    float4* Ws4 = (float4*)Ws;
    const float4* W4  = (const float4*)W;
    const float4* in4 = (const float4*)in;
    const float4* b4  = (const float4*)bias;

    unsigned long long acc2[8][4];
#pragma unroll
    for (int r = 0; r < 8; r++)
#pragma unroll
        for (int c = 0; c < 4; c++) acc2[r][c] = 0ull;

    for (int kk = 0; kk < 128; kk += 32) {
#pragma unroll
        for (int i = tid; i < 1024; i += 256)
            Ws4[i] = W4[(kk + (i >> 5)) * 32 + (i & 31)];
#pragma unroll
        for (int i = tid; i < 1024; i += 256) {
            int row = i >> 3, j = i & 7;
            int gr = r0 + row;
            float4 v = make_float4(0.f, 0.f, 0.f, 0.f);
            if (gr < NN) {
                v = in4[gr * 32 + (kk >> 2) + j];
                if (bias) {
                    float4 bb = b4[(kk >> 2) + j];
                    v.x = fmaxf(v.x + bb.x, 0.f);
                    v.y = fmaxf(v.y + bb.y, 0.f);
                    v.z = fmaxf(v.z + bb.z, 0.f);
                    v.w = fmaxf(v.w + bb.w, 0.f);
                }
            }
            float* xp = &Xs[row * 33 + j * 4];
            xp[0] = v.x; xp[1] = v.y; xp[2] = v.z; xp[3] = v.w;
        }
        __syncthreads();

#pragma unroll
        for (int k = 0; k < 32; k++) {
            float4 wa = Ws4[k * 32 + cg * 2];
            float4 wb = Ws4[k * 32 + cg * 2 + 1];
            unsigned long long w0 = pk2(wa.x, wa.y);
            unsigned long long w1 = pk2(wa.z, wa.w);
            unsigned long long w2 = pk2(wb.x, wb.y);
            unsigned long long w3 = pk2(wb.z, wb.w);
#pragma unroll
            for (int r = 0; r < 8; r++) {
                float xv = Xs[(rg * 8 + r) * 33 + k];
                unsigned long long xp = pk2(xv, xv);
                fma2(acc2[r][0], xp, w0);
                fma2(acc2[r][1], xp, w1);
                fma2(acc2[r][2], xp, w2);
                fma2(acc2[r][3], xp, w3);
            }
        }
        __syncthreads();
    }

    const float4* as4 = (const float4*)as;
    const float4* ad4 = (const float4*)ad;
    float4 A0 = as4[cg * 2], A1 = as4[cg * 2 + 1];
    float4 D0 = ad4[cg * 2], D1 = ad4[cg * 2 + 1];
    float4* out4 = (float4*)g_h;
    float mxl = -INFINITY;
    const int head = cg >> 2;
    const bool lead = (cg & 3) == 0;

#pragma unroll
    for (int r = 0; r < 8; r++) {
        float a0, a1, a2, a3, a4, a5, a6, a7;
        upk2(acc2[r][0], a0, a1);
        upk2(acc2[r][1], a2, a3);
        upk2(acc2[r][2], a4, a5);
        upk2(acc2[r][3], a6, a7);
        float ps = a0 * A0.x + a1 * A0.y + a2 * A0.z + a3 * A0.w
                 + a4 * A1.x + a5 * A1.y + a6 * A1.z + a7 * A1.w;
        float pd = a0 * D0.x + a1 * D0.y + a2 * D0.z + a3 * D0.w
                 + a4 * D1.x + a5 * D1.y + a6 * D1.z + a7 * D1.w;
        ps += __shfl_xor_sync(0xffffffffu, ps, 1);
        ps += __shfl_xor_sync(0xffffffffu, ps, 2);
        pd += __shfl_xor_sync(0xffffffffu, pd, 1);
        pd += __shfl_xor_sync(0xffffffffu, pd, 2);
        int gr = r0 + rg * 8 + r;
        if (gr < NN) {
            out4[gr * 32 + cg * 2]     = make_float4(a0, a1, a2, a3);
            out4[gr * 32 + cg * 2 + 1] = make_float4(a4, a5, a6, a7);
            if (lead) {
                g_asrc[gr * 4 + head] = ps;
                g_adst[gr * 4 + head] = pd;
                mxl = fmaxf(mxl, ps);
            }
        }
    }

    __syncthreads();
    float* sred = Xs;
    sred[tid] = mxl;
    __syncthreads();
    for (int s = 128; s; s >>= 1) {
        if (tid < s) sred[tid] = fmaxf(sred[tid], sred[tid + s]);
        __syncthreads();
    }
    if (tid == 0) atomicMax(&g_gmax_enc[layer], fenc(sred[0]));
}

// ---------------- fused softmax + aggregation: 4 dst nodes per warp ----------------
// (round-13 proven, FROZEN)
__global__ __launch_bounds__(256) void k_aggr(int layer,
                                              const void* __restrict__ batch,
                                              const float* __restrict__ b2) {
    int w    = (blockIdx.x * blockDim.x + threadIdx.x) >> 5;
    int lane = threadIdx.x & 31;
    int grp  = lane >> 3;
    int gl   = lane & 7;
    int d    = w * 4 + grp;
    if (d >= NN) return;

    float gmax = fdec(g_gmax_enc[layer]);
    float4 adv = ((const float4*)g_adst)[d];
    float m0 = lrelu(gmax + adv.x);
    float m1 = lrelu(gmax + adv.y);
    float m2 = lrelu(gmax + adv.z);
    float m3 = lrelu(gmax + adv.w);

    int beg = g_row[d];
    int cnt = g_row[d + 1] - beg;
    if (layer == 0 && gl == 0) g_deg[d] = 0;    // leave-clean for next call

    int tmax = cnt;
    tmax = max(tmax, __shfl_xor_sync(0xffffffffu, tmax, 8));
    tmax = max(tmax, __shfl_xor_sync(0xffffffffu, tmax, 16));

    float4 acc0 = make_float4(0.f, 0.f, 0.f, 0.f);
    float4 acc1 = acc0, acc2 = acc0, acc3 = acc0;
    float den0 = 0.f, den1 = 0.f, den2 = 0.f, den3 = 0.f;
    const float4* h4  = (const float4*)g_h;
    const float4* as4 = (const float4*)g_asrc;

    for (int t = 0; t < tmax; t += 2) {
#pragma unroll
        for (int u = 0; u < 2; u++) {
            int tt = t + u;
            if (tt < cnt) {
                int s = g_csr[beg + tt];
                float4 av = as4[s];
                float e0 = __expf(lrelu(av.x + adv.x) - m0);
                float e1 = __expf(lrelu(av.y + adv.y) - m1);
                float e2 = __expf(lrelu(av.z + adv.z) - m2);
                float e3 = __expf(lrelu(av.w + adv.w) - m3);
                float4 h0 = h4[s * 32 + gl];
                float4 h1 = h4[s * 32 + gl + 8];
                float4 h2 = h4[s * 32 + gl + 16];
                float4 h3 = h4[s * 32 + gl + 24];
                den0 += e0; den1 += e1; den2 += e2; den3 += e3;
                acc0.x += e0 * h0.x; acc0.y += e0 * h0.y; acc0.z += e0 * h0.z; acc0.w += e0 * h0.w;
                acc1.x += e1 * h1.x; acc1.y += e1 * h1.y; acc1.z += e1 * h1.z; acc1.w += e1 * h1.w;
                acc2.x += e2 * h2.x; acc2.y += e2 * h2.y; acc2.z += e2 * h2.z; acc2.w += e2 * h2.w;
                acc3.x += e3 * h3.x; acc3.y += e3 * h3.y; acc3.z += e3 * h3.z; acc3.w += e3 * h3.w;
            }
        }
    }
    // self loop (s = d)
    {
        float4 av = as4[d];
        float e0 = __expf(lrelu(av.x + adv.x) - m0);
        float e1 = __expf(lrelu(av.y + adv.y) - m1);
        float e2 = __expf(lrelu(av.z + adv.z) - m2);
        float e3 = __expf(lrelu(av.w + adv.w) - m3);
        float4 h0 = h4[d * 32 + gl];
        float4 h1 = h4[d * 32 + gl + 8];
        float4 h2 = h4[d * 32 + gl + 16];
        float4 h3 = h4[d * 32 + gl + 24];
        den0 += e0; den1 += e1; den2 += e2; den3 += e3;
        acc0.x += e0 * h0.x; acc0.y += e0 * h0.y; acc0.z += e0 * h0.z; acc0.w += e0 * h0.w;
        acc1.x += e1 * h1.x; acc1.y += e1 * h1.y; acc1.z += e1 * h1.z; acc1.w += e1 * h1.w;
        acc2.x += e2 * h2.x; acc2.y += e2 * h2.y; acc2.z += e2 * h2.z; acc2.w += e2 * h2.w;
        acc3.x += e3 * h3.x; acc3.y += e3 * h3.y; acc3.z += e3 * h3.z; acc3.w += e3 * h3.w;
    }

    float i0 = 1.f / den0, i1 = 1.f / den1, i2 = 1.f / den2, i3 = 1.f / den3;
    float4 o0 = make_float4(acc0.x * i0, acc0.y * i0, acc0.z * i0, acc0.w * i0);
    float4 o1 = make_float4(acc1.x * i1, acc1.y * i1, acc1.z * i1, acc1.w * i1);
    float4 o2 = make_float4(acc2.x * i2, acc2.y * i2, acc2.z * i2, acc2.w * i2);
    float4 o3 = make_float4(acc3.x * i3, acc3.y * i3, acc3.z * i3, acc3.w * i3);

    if (layer < 2) {
        float4* out4 = (float4*)g_out;
        out4[d * 32 + gl]      = o0;
        out4[d * 32 + gl + 8]  = o1;
        out4[d * 32 + gl + 16] = o2;
        out4[d * 32 + gl + 24] = o3;
    } else {
        int g = g_is64 ? (int)((const long long*)batch)[d] : ((const int*)batch)[d];
        const float4* b24 = (const float4*)b2;
        float4 bb0 = b24[gl], bb1 = b24[gl + 8], bb2 = b24[gl + 16], bb3 = b24[gl + 24];
        int* pp = (int*)&g_pool[g * 128];
#pragma unroll 4
        for (int i = 0; i < 4; i++) {
            float4 o  = (i == 0) ? o0 : (i == 1) ? o1 : (i == 2) ? o2 : o3;
            float4 bb = (i == 0) ? bb0 : (i == 1) ? bb1 : (i == 2) ? bb2 : bb3;
            int c = (gl + 8 * i) * 4;
            atomicMax(&pp[c + 0], __float_as_int(fmaxf(o.x + bb.x, 0.f)));
            atomicMax(&pp[c + 1], __float_as_int(fmaxf(o.y + bb.y, 0.f)));
            atomicMax(&pp[c + 2], __float_as_int(fmaxf(o.z + bb.z, 0.f)));
            atomicMax(&pp[c + 3], __float_as_int(fmaxf(o.w + bb.w, 0.f)));
        }
    }
}

// ---------------- fused MLP tail: per-graph block ----------------
__global__ __launch_bounds__(256) void k_lin(const float* __restrict__ Wlin,
                                             const float* __restrict__ blin,
                                             const float* __restrict__ Wout,
                                             const float* __restrict__ bout,
                                             float* __restrict__ out) {
    __shared__ float sp[128];
    __shared__ float z[256];
    int g = blockIdx.x, t = threadIdx.x;
    if (t < 128) sp[t] = g_pool[g * 128 + t];
    __syncthreads();
    float acc = blin[t];
    for (int k = 0; k < 128; k++) acc += sp[k] * Wlin[k * 256 + t];
    z[t] = acc;
    __syncthreads();
    if (t < OUTW) {
        float o = bout[t];
        for (int k = 0; k < 256; k++) o += z[k] * Wout[k * OUTW + t];
        out[g * OUTW + t] = o;
    }
}

// ---------------- host launcher: fork CSR build parallel to layer-0 GEMM ----------------
extern "C" void kernel_launch(void* const* d_in, const int* in_sizes, int n_in,
                              void* d_out, int out_size) {
    const float* x    = (const float*)d_in[0];
    const void*  ei   = d_in[1];
    const void*  batch= d_in[2];
    const float* W0   = (const float*)d_in[3];
    const float* as0  = (const float*)d_in[4];
    const float* ad0  = (const float*)d_in[5];
    const float* b0   = (const float*)d_in[6];
    const float* W1   = (const float*)d_in[7];
    const float* as1  = (const float*)d_in[8];
    const float* ad1  = (const float*)d_in[9];
    const float* b1   = (const float*)d_in[10];
    const float* W2   = (const float*)d_in[11];
    const float* as2  = (const float*)d_in[12];
    const float* ad2  = (const float*)d_in[13];
    const float* b2   = (const float*)d_in[14];
    const float* Wlin = (const float*)d_in[15];
    const float* blin = (const float*)d_in[16];
    const float* Wout = (const float*)d_in[17];
    const float* bout = (const float*)d_in[18];

    const float* Ws[3]  = {W0, W1, W2};
    const float* ass[3] = {as0, as1, as2};
    const float* ads[3] = {ad0, ad1, ad2};
    const float* bp[3]  = {nullptr, b0, b1};

    cudaStream_t s2;
    cudaStreamCreateWithFlags(&s2, cudaStreamNonBlocking);
    cudaEvent_t evFork, evJoin;
    cudaEventCreateWithFlags(&evFork, cudaEventDisableTiming);
    cudaEventCreateWithFlags(&evJoin, cudaEventDisableTiming);

    const int gemm_blocks = (NN + 127) / 128;
    const int aggr_blocks = ((NN + 3) / 4 * 32 + 255) / 256;

    // common root: init (writes g_is64 needed by CSR branch, gmax for gemm)
    k_init<<<32, 256>>>((const unsigned*)ei);

    // fork: CSR build on s2
    cudaEventRecord(evFork, 0);
    cudaStreamWaitEvent(s2, evFork, 0);
    k_hist<<<(EE + 255) / 256, 256, 0, s2>>>(ei);
    k_scan1<<<SB, 1024, 0, s2>>>();
    k_scan3<<<SB, 1024, 0, s2>>>();
    k_scatter<<<(EE + 255) / 256, 256, 0, s2>>>(ei);
    cudaEventRecord(evJoin, s2);

    // main branch: layer-0 GEMM (independent of CSR)
    k_gemm<<<gemm_blocks, 256>>>(x, Ws[0], bp[0], 0, ass[0], ads[0], 0);

    // join: aggregation needs both
    cudaStreamWaitEvent(0, evJoin, 0);
    k_aggr<<<aggr_blocks, 256>>>(0, batch, b2);

    for (int l = 1; l < 3; l++) {
        k_gemm<<<gemm_blocks, 256>>>(x, Ws[l], bp[l], 1, ass[l], ads[l], l);
        k_aggr<<<aggr_blocks, 256>>>(l, batch, b2);
    }

    k_lin<<<GG, 256>>>(Wlin, blin, Wout, bout, (float*)d_out);

    // cleanup only outside graph capture (destroy during capture is illegal;
    // capture happens on a bounded number of calls, so any leak is bounded)
    cudaStreamCaptureStatus st = cudaStreamCaptureStatusNone;
    cudaStreamIsCapturing(0, &st);
    if (st == cudaStreamCaptureStatusNone) {
        cudaStreamDestroy(s2);
        cudaEventDestroy(evFork);
        cudaEventDestroy(evJoin);
    }
}